// round 3
// baseline (speedup 1.0000x reference)
#include <cuda_runtime.h>
#include <cstdint>

#define DEVINL __device__ __forceinline__

// ---------------- tile config ----------------
static constexpr int BM = 128, BN = 128, BK = 128;     // int8: K tile = 128 bytes
static constexpr int STAGES = 3;
static constexpr int THREADS = 256;                    // 8 warps: 2 (M) x 4 (N), warp tile 64x32
static constexpr int A_BYTES = BM * BK;                // 16384
static constexpr int B_BYTES = BN * BK;                // 16384
static constexpr int STAGE_BYTES = A_BYTES + B_BYTES;  // 32768
static constexpr int SMEM_FRS = STAGES * STAGE_BYTES;  // 98304: 128 floats scale_A/scale_out ratio
static constexpr int SMEM_SBF = SMEM_FRS + 512;        // 128 floats scale_B
static constexpr int SMEM_TOTAL = SMEM_SBF + 512;      // 99328

static constexpr int MAX_M = 8192, MAX_K = 4096, MAX_N = 4096;

// s8 copies of the int32-stored operands (device-global scratch: allowed)
__device__ __align__(128) int8_t g_A8[(size_t)MAX_M * MAX_K];
__device__ __align__(128) int8_t g_B8[(size_t)MAX_N * MAX_K];

// ---------------- helpers ----------------
DEVINL uint32_t smem_u32(const void* p) {
    uint32_t a;
    asm("{ .reg .u64 t; cvta.to.shared.u64 t, %1; cvt.u32.u64 %0, t; }" : "=r"(a) : "l"(p));
    return a;
}

DEVINL void cp16(uint32_t s, const void* g) {
    asm volatile("cp.async.cg.shared.global [%0], [%1], 16;" :: "r"(s), "l"(g) : "memory");
}

DEVINL void ldm_x4(uint32_t& r0, uint32_t& r1, uint32_t& r2, uint32_t& r3, uint32_t addr) {
    asm volatile("ldmatrix.sync.aligned.m8n8.x4.shared.b16 {%0,%1,%2,%3}, [%4];"
                 : "=r"(r0), "=r"(r1), "=r"(r2), "=r"(r3) : "r"(addr));
}

DEVINL void mma_s8(int* c, const uint32_t* a, const uint32_t* b) {
    asm volatile(
        "mma.sync.aligned.m16n8k32.row.col.s32.s8.s8.s32 "
        "{%0,%1,%2,%3}, {%4,%5,%6,%7}, {%8,%9}, {%0,%1,%2,%3};"
        : "+r"(c[0]), "+r"(c[1]), "+r"(c[2]), "+r"(c[3])
        : "r"(a[0]), "r"(a[1]), "r"(a[2]), "r"(a[3]), "r"(b[0]), "r"(b[1]));
}

// ---------------- int32 -> int8 repack ----------------
__global__ void cvt_kernel(const int4* __restrict__ in, uint32_t* __restrict__ out, int n) {
    int i = blockIdx.x * blockDim.x + threadIdx.x;
    if (i < n) {
        int4 v = in[i];
        out[i] = (uint32_t)(v.x & 255) | ((uint32_t)(v.y & 255) << 8) |
                 ((uint32_t)(v.z & 255) << 16) | ((uint32_t)(v.w & 255) << 24);
    }
}

// ---------------- main GEMM kernel ----------------
// FOUT=true: C is float32 (int8 result value-cast to float). FOUT=false: C is int8.
template <bool FOUT>
__global__ __launch_bounds__(THREADS, 2) void i8gemm_kernel(
    const float* __restrict__ scale_A, const float* __restrict__ scale_B,
    const float* __restrict__ scale_out, void* __restrict__ Cout,
    int M, int N, int K, int tilesN)
{
    extern __shared__ __align__(1024) uint8_t smem[];
    const uint32_t sb = smem_u32(smem);
    const int tid = threadIdx.x;
    const int lane = tid & 31, wrp = tid >> 5;
    const int warpM = wrp >> 2, warpN = wrp & 3;   // 2 x 4 warp grid, warp tile 64x32

    // grid swizzle: groups of 8 M-tiles share B tiles within a wave (L2 reuse)
    const int GM = 8;
    const int bid = blockIdx.x;
    const int group = bid / (GM * tilesN);
    const int rem = bid % (GM * tilesN);
    const int mt = group * GM + (rem % GM);
    const int nt = rem / GM;
    const int m0 = mt * BM, n0 = nt * BN;
    const int NT = K / BK;

    // per-row dequant ratio + per-col scale into smem
    float* frs = reinterpret_cast<float*>(smem + SMEM_FRS);
    float* sbf = reinterpret_cast<float*>(smem + SMEM_SBF);
    if (tid < 128) {
        frs[tid] = __fdiv_rn(scale_A[m0 + tid], scale_out[m0 + tid]);  // IEEE, matches jax fp32
        sbf[tid] = scale_B[n0 + tid];
    }

    const int8_t* gA0 = g_A8 + (size_t)m0 * K;
    const int8_t* gB0 = g_B8 + (size_t)n0 * K;

    auto produce = [&](int stage, int kt) {
        const int8_t* gA = gA0 + kt * BK;
        const int8_t* gB = gB0 + kt * BK;
        const uint32_t baseA = sb + (uint32_t)stage * STAGE_BYTES;
        const uint32_t baseB = baseA + A_BYTES;
#pragma unroll
        for (int i = 0; i < 4; i++) {
            const int cid = i * THREADS + tid;         // 0..1023
            const int row = cid >> 3, c16 = cid & 7;
            const uint32_t so = (uint32_t)(row * 128) + (uint32_t)((c16 ^ (row & 7)) << 4);
            cp16(baseA + so, gA + (size_t)row * K + c16 * 16);
        }
#pragma unroll
        for (int i = 0; i < 4; i++) {
            const int cid = i * THREADS + tid;
            const int row = cid >> 3, c16 = cid & 7;
            const uint32_t so = (uint32_t)(row * 128) + (uint32_t)((c16 ^ (row & 7)) << 4);
            cp16(baseB + so, gB + (size_t)row * K + c16 * 16);
        }
        asm volatile("cp.async.commit_group;" ::: "memory");
    };

    // accumulators: 4 (mi) x 4 (ni) x 4 regs
    int c[4][4][4];
#pragma unroll
    for (int mi = 0; mi < 4; mi++)
#pragma unroll
        for (int ni = 0; ni < 4; ni++)
#pragma unroll
            for (int j = 0; j < 4; j++) c[mi][ni][j] = 0;

    // ldmatrix per-lane geometry (identical for A and B)
    const int rl = (lane & 7) | (((lane >> 3) & 1) << 3);
    const int kh = (lane >> 4) << 4;                 // 0 or 16 bytes
    const uint32_t xorv = (uint32_t)((rl & 7) << 4); // SW128 xor term
    const uint32_t aRow = (uint32_t)((warpM * 64 + rl) * 128);
    const uint32_t bRow = (uint32_t)((warpN * 32 + rl) * 128);

    // prologue
    produce(0, 0);
    produce(1, 1);

    for (int kt = 0; kt < NT; kt++) {
        asm volatile("cp.async.wait_group 1;" ::: "memory");
        __syncthreads();

        const int kf = kt + STAGES - 1;
        if (kf < NT) produce(kf % STAGES, kf);
        else asm volatile("cp.async.commit_group;" ::: "memory");

        const uint32_t Ab = sb + (uint32_t)(kt % STAGES) * STAGE_BYTES;
        const uint32_t Bb = Ab + A_BYTES;

#pragma unroll
        for (int ks = 0; ks < 4; ks++) {             // 4 x K=32 per 128B K tile
            const uint32_t kx = (uint32_t)((ks * 32 + kh)) ^ xorv;
            uint32_t a[4][4];
#pragma unroll
            for (int mi = 0; mi < 4; mi++)
                ldm_x4(a[mi][0], a[mi][1], a[mi][2], a[mi][3],
                       Ab + aRow + (uint32_t)(mi * 2048) + kx);
            uint32_t b[4][2];
#pragma unroll
            for (int nip = 0; nip < 2; nip++) {
                uint32_t r0, r1, r2, r3;
                ldm_x4(r0, r1, r2, r3, Bb + bRow + (uint32_t)(nip * 2048) + kx);
                b[2 * nip][0] = r0; b[2 * nip][1] = r2;
                b[2 * nip + 1][0] = r1; b[2 * nip + 1][1] = r3;
            }
#pragma unroll
            for (int mi = 0; mi < 4; mi++)
#pragma unroll
                for (int ni = 0; ni < 4; ni++)
                    mma_s8(c[mi][ni], a[mi], b[ni]);
        }
    }

    asm volatile("cp.async.wait_group 0;" ::: "memory");
    __syncthreads();   // pipeline smem now reusable as epilogue staging

    // ------------- epilogue: dequant -> round -> clip -> pack -------------
    // c-fragment m16n8 s32: c0,c1 = row (lane>>2), cols (lane&3)*2, +1 ; c2,c3 = row+8
    const int l4 = lane >> 2, lm = lane & 3;
    uint8_t* stg = smem;   // 16KB staging in stage-0 region

#pragma unroll
    for (int mi = 0; mi < 4; mi++) {
#pragma unroll
        for (int h = 0; h < 2; h++) {
            const int row = warpM * 64 + mi * 16 + l4 + h * 8;
            const float fr = frs[row];
#pragma unroll
            for (int ni = 0; ni < 4; ni++) {
                const int colb = warpN * 32 + ni * 8 + lm * 2;
                const float s0 = sbf[colb], s1 = sbf[colb + 1];
                const int acc0 = c[mi][ni][2 * h], acc1 = c[mi][ni][2 * h + 1];
                float x0 = __fmul_rn(__fmul_rn((float)acc0, fr), s0);
                float x1 = __fmul_rn(__fmul_rn((float)acc1, fr), s1);
                int v0 = __float2int_rn(x0);         // round-half-even == jnp.round
                int v1 = __float2int_rn(x1);
                v0 = v0 < -128 ? -128 : (v0 > 127 ? 127 : v0);
                v1 = v1 < -128 ? -128 : (v1 > 127 ? 127 : v1);
                const uint16_t pk = (uint16_t)((v0 & 255) | ((v1 & 255) << 8));
                const int w = colb >> 2, bb = colb & 3;
                *reinterpret_cast<uint16_t*>(
                    stg + row * 128 + ((w ^ (row & 31)) << 2) + bb) = pk;
            }
        }
    }
    __syncthreads();

    // coalesced output: 128 rows x 32 words, conflict-free swizzled LDS
#pragma unroll
    for (int i = 0; i < 16; i++) {
        const int idx = i * THREADS + tid;
        const int row = idx >> 5, w = idx & 31;
        const uint32_t v = *reinterpret_cast<const uint32_t*>(
            stg + row * 128 + ((w ^ (row & 31)) << 2));
        if (FOUT) {
            float4 f;
            f.x = (float)(int)(int8_t)(v & 255);
            f.y = (float)(int)(int8_t)((v >> 8) & 255);
            f.z = (float)(int)(int8_t)((v >> 16) & 255);
            f.w = (float)(int)(int8_t)((v >> 24) & 255);
            *reinterpret_cast<float4*>(
                (float*)Cout + (size_t)(m0 + row) * N + n0 + w * 4) = f;
        } else {
            *reinterpret_cast<uint32_t*>(
                (int8_t*)Cout + (size_t)(m0 + row) * N + n0 + w * 4) = v;
        }
    }
}

// ---------------- launch ----------------
extern "C" void kernel_launch(void* const* d_in, const int* in_sizes, int n_in,
                              void* d_out, int out_size) {
    const int*   A  = (const int*)d_in[0];
    const float* sA = (const float*)d_in[1];
    const int*   B  = (const int*)d_in[2];
    const float* sB = (const float*)d_in[3];
    const float* so = (const float*)d_in[4];

    const int M = in_sizes[1];            // |scale_A|
    const int N = in_sizes[3];            // |scale_B|
    const int K = in_sizes[0] / M;

    void* pA = nullptr; void* pB = nullptr;
    cudaGetSymbolAddress(&pA, g_A8);
    cudaGetSymbolAddress(&pB, g_B8);

    const int nA = (M * K) / 4;
    const int nB = (N * K) / 4;
    cvt_kernel<<<(nA + 255) / 256, 256>>>((const int4*)A, (uint32_t*)pA, nA);
    cvt_kernel<<<(nB + 255) / 256, 256>>>((const int4*)B, (uint32_t*)pB, nB);

    const int tilesM = M / BM, tilesN = N / BN;
    const size_t MN = (size_t)M * N;
    const long long extra = (long long)out_size - (long long)MN;

    if (extra == (long long)M) {
        // float32 output buffer: C values (int8 result, value-cast) + scale_out floats
        cudaFuncSetAttribute(i8gemm_kernel<true>,
                             cudaFuncAttributeMaxDynamicSharedMemorySize, SMEM_TOTAL);
        i8gemm_kernel<true><<<tilesM * tilesN, THREADS, SMEM_TOTAL>>>(
            sA, sB, so, d_out, M, N, K, tilesN);
        cudaMemcpyAsync((float*)d_out + MN, so, sizeof(float) * (size_t)M,
                        cudaMemcpyDeviceToDevice);
    } else {
        // int8 output buffer (optionally with raw scale_out byte tail)
        cudaFuncSetAttribute(i8gemm_kernel<false>,
                             cudaFuncAttributeMaxDynamicSharedMemorySize, SMEM_TOTAL);
        i8gemm_kernel<false><<<tilesM * tilesN, THREADS, SMEM_TOTAL>>>(
            sA, sB, so, d_out, M, N, K, tilesN);
        if (extra == (long long)4 * M) {
            cudaMemcpyAsync((int8_t*)d_out + MN, so, sizeof(float) * (size_t)M,
                            cudaMemcpyDeviceToDevice);
        } else if (extra > 0) {
            cudaMemsetAsync((int8_t*)d_out + MN, 0, (size_t)extra);
        }
    }
}